// round 3
// baseline (speedup 1.0000x reference)
#include <cuda_runtime.h>
#include <math.h>

#define NQ 8
#define NF 256
#define NPAIR 28
#define MAXN 50176
#define MAXE 1600000
#define TILE 4096
#define GRAMB 148

// ---------------- static scratch (no dynamic allocation allowed) ----------------
__device__ float g_feat [MAXN * NPAIR];   // raw features
__device__ float g_sfeat[MAXN * NPAIR];   // dinv-scaled features
__device__ float g_agg  [MAXN * NPAIR];   // relu(aggregated)
__device__ int   g_cnt [MAXN];            // in-degree (excl self loop)
__device__ int   g_off [MAXN];            // CSR offsets
__device__ int   g_cur [MAXN];            // fill cursors
__device__ int   g_srcidx[MAXE];          // CSR: source node per in-edge
__device__ float g_dinv[MAXN];
__device__ float g_coefs[NPAIR * 4];      // (B00, -B00, 2ReB01, pad) per pair
__device__ int   g_tsum[64];              // scan tile sums
__device__ int   g_tpre[64];              // scan tile exclusive prefixes
__device__ float g_Gpart[784 * GRAMB];    // gram partials, [e*GRAMB + b]
__device__ float g_G[784];

// 'a' (first qubit) of each pair in combinations(range(8),2) order
__constant__ int c_pair_a[NPAIR] = {
    0,0,0,0,0,0,0, 1,1,1,1,1,1, 2,2,2,2,2, 3,3,3,3, 4,4,4, 5,5, 6
};

// ---------------- complex 2x2 helpers ----------------
__device__ __forceinline__ float2 cmul(float2 a, float2 b) {
    return make_float2(a.x * b.x - a.y * b.y, a.x * b.y + a.y * b.x);
}
__device__ __forceinline__ float2 cadd(float2 a, float2 b) {
    return make_float2(a.x + b.x, a.y + b.y);
}
__device__ __forceinline__ void mm2(const float2* A, const float2* B, float2* C) {
#pragma unroll
    for (int i = 0; i < 2; i++)
#pragma unroll
        for (int j = 0; j < 2; j++)
            C[i * 2 + j] = cadd(cmul(A[i * 2 + 0], B[0 * 2 + j]),
                                cmul(A[i * 2 + 1], B[1 * 2 + j]));
}

// K1: B = A^dag Z A coefficients for 28 pairs (1 warp)
__global__ void k_setup(const float* __restrict__ qw) {
    int t = threadIdx.x;
    if (t >= NPAIR) return;
    const float* p = qw + 6 * t;
    float2 M[4], T[4], R[4];
    float c, s;
    c = cosf(0.5f * p[0]); s = sinf(0.5f * p[0]);
    M[0] = make_float2(c, 0); M[1] = make_float2(0, -s);
    M[2] = make_float2(0, -s); M[3] = make_float2(c, 0);            // Rx(p0)
    c = cosf(0.5f * p[1]); s = sinf(0.5f * p[1]);
    R[0] = make_float2(c, 0); R[1] = make_float2(-s, 0);
    R[2] = make_float2(s, 0); R[3] = make_float2(c, 0);
    mm2(R, M, T);                                                   // Ry(p1)·
    c = cosf(0.5f * p[2]); s = sinf(0.5f * p[2]);
    R[0] = make_float2(c, -s); R[1] = make_float2(0, 0);
    R[2] = make_float2(0, 0);  R[3] = make_float2(c, s);
    mm2(R, T, M);                                                   // Rz(p2)·
    c = cosf(0.5f * p[3]); s = sinf(0.5f * p[3]);
    R[0] = make_float2(c, 0); R[1] = make_float2(0, -s);
    R[2] = make_float2(0, -s); R[3] = make_float2(c, 0);
    mm2(R, M, T);                                                   // Rx(p3)·
    c = cosf(0.5f * p[4]); s = sinf(0.5f * p[4]);
    R[0] = make_float2(c, 0); R[1] = make_float2(-s, 0);
    R[2] = make_float2(s, 0); R[3] = make_float2(c, 0);
    mm2(R, T, M);                                                   // Ry(p4)·
    c = cosf(0.5f * p[5]); s = sinf(0.5f * p[5]);
    R[0] = make_float2(c, -s); R[1] = make_float2(0, 0);
    R[2] = make_float2(0, 0);  R[3] = make_float2(c, s);
    mm2(R, M, T);                                                   // T = A
    float b00 = T[0].x * T[0].x + T[0].y * T[0].y
              - (T[2].x * T[2].x + T[2].y * T[2].y);
    float b01x2 = 2.f * (T[0].x * T[1].x + T[0].y * T[1].y
                       - T[2].x * T[3].x - T[2].y * T[3].y);
    g_coefs[t * 4 + 0] = b00;
    g_coefs[t * 4 + 1] = -b00;
    g_coefs[t * 4 + 2] = b01x2;
}

// K2: per-node single-qubit moments -> 28 features. One warp per node.
__global__ void k_feat(const float* __restrict__ x, int N) {
    __shared__ float sx[8 * NF];
    int warp = threadIdx.x >> 5;
    int lane = threadIdx.x & 31;
    int node = blockIdx.x * 8 + warp;
    if (node >= N) return;                      // warp-uniform exit
    float* row = sx + warp * NF;
    const float* xr = x + (size_t)node * NF;
#pragma unroll
    for (int k = 0; k < 8; k++)
        row[lane + 32 * k] = xr[lane + 32 * k];
    __syncwarp();

    float ss = 0.f;
    float sm[8] = {0, 0, 0, 0, 0, 0, 0, 0};     // sum x^2 * (-1)^{bit_q}
    float Tq[8] = {0, 0, 0, 0, 0, 0, 0, 0};     // sum x_i x_{i^mask_q}, bit_q=0
#pragma unroll
    for (int k = 0; k < 8; k++) {
        int i = lane + 32 * k;
        float v = row[i];
        float v2 = v * v;
        ss += v2;
#pragma unroll
        for (int q = 0; q < 8; q++)
            sm[q] += ((i >> (7 - q)) & 1) ? -v2 : v2;
    }
#pragma unroll
    for (int q = 0; q < 8; q++) {
        const int pos = 7 - q;
#pragma unroll
        for (int t = 0; t < 4; t++) {
            int idx = lane + 32 * t;                                  // 0..127
            int i = ((idx >> pos) << (pos + 1)) | (idx & ((1 << pos) - 1));
            Tq[q] += row[i] * row[i + (1 << pos)];
        }
    }
#pragma unroll
    for (int off = 16; off; off >>= 1) {
        ss += __shfl_xor_sync(0xffffffffu, ss, off);
#pragma unroll
        for (int q = 0; q < 8; q++) {
            sm[q] += __shfl_xor_sync(0xffffffffu, sm[q], off);
            Tq[q] += __shfl_xor_sync(0xffffffffu, Tq[q], off);
        }
    }
    if (lane < NPAIR) {
        int a = c_pair_a[lane];
        float S = 0.f, Tv = 0.f;
#pragma unroll
        for (int q = 0; q < 8; q++)
            if (a == q) { S = sm[q]; Tv = Tq[q]; }
        float S0 = 0.5f * (ss + S);
        float S1 = ss - S0;
        float e = (g_coefs[lane * 4 + 0] * S0 + g_coefs[lane * 4 + 1] * S1
                 + g_coefs[lane * 4 + 2] * Tv) / ss;
        g_feat[(size_t)node * NPAIR + lane] = 0.5f + 0.5f * e;
    }
}

// K3: zero counters
__global__ void k_zero(int N) {
    int i = blockIdx.x * blockDim.x + threadIdx.x;
    if (i < N) g_cnt[i] = 0;
}

// K4: in-degree histogram (edge_index is int32!)
__global__ void k_hist(const int* __restrict__ dst, int E, int N) {
    int e = blockIdx.x * blockDim.x + threadIdx.x;
    if (e >= E) return;
    unsigned d = (unsigned)dst[e];
    if (d < (unsigned)N) atomicAdd(&g_cnt[d], 1);
}

// K5a: per-tile sums (TILE=4096 elems, 1024 threads x 4)
__global__ void k_scanA(int N) {
    __shared__ int sred[32];
    int b = blockIdx.x, t = threadIdx.x;
    int lane = t & 31, warp = t >> 5;
    int base = b * TILE + t * 4;
    int s = 0;
#pragma unroll
    for (int k = 0; k < 4; k++) {
        int i = base + k;
        s += (i < N) ? g_cnt[i] : 0;
    }
#pragma unroll
    for (int off = 16; off; off >>= 1) s += __shfl_xor_sync(~0u, s, off);
    if (lane == 0) sred[warp] = s;
    __syncthreads();
    if (warp == 0) {
        int v = sred[lane];
#pragma unroll
        for (int off = 16; off; off >>= 1) v += __shfl_xor_sync(~0u, v, off);
        if (lane == 0) g_tsum[b] = v;
    }
}

// K5b: exclusive scan of tile sums (1 warp, up to 32 tiles)
__global__ void k_scanB(int ntiles) {
    int t = threadIdx.x;
    int v = (t < ntiles) ? g_tsum[t] : 0;
    int incl = v;
#pragma unroll
    for (int off = 1; off < 32; off <<= 1) {
        int u = __shfl_up_sync(~0u, incl, off);
        if (t >= off) incl += u;
    }
    if (t < ntiles) g_tpre[t] = incl - v;
}

// K5c: apply scan -> offsets, cursors, dinv
__global__ void k_scanC(int N) {
    __shared__ int swsum[32];
    __shared__ int swpre[32];
    int b = blockIdx.x, t = threadIdx.x;
    int lane = t & 31, warp = t >> 5;
    int base = b * TILE + t * 4;
    int v[4], pre[4];
    int run = 0;
#pragma unroll
    for (int k = 0; k < 4; k++) {
        int i = base + k;
        v[k] = (i < N) ? g_cnt[i] : 0;
        pre[k] = run;
        run += v[k];
    }
    int incl = run;
#pragma unroll
    for (int off = 1; off < 32; off <<= 1) {
        int u = __shfl_up_sync(~0u, incl, off);
        if (lane >= off) incl += u;
    }
    if (lane == 31) swsum[warp] = incl;
    int texcl = incl - run;
    __syncthreads();
    if (warp == 0) {
        int w = swsum[lane];
        int wi = w;
#pragma unroll
        for (int off = 1; off < 32; off <<= 1) {
            int u = __shfl_up_sync(~0u, wi, off);
            if (lane >= off) wi += u;
        }
        swpre[lane] = wi - w;
    }
    __syncthreads();
    int tilebase = g_tpre[b] + swpre[warp] + texcl;
#pragma unroll
    for (int k = 0; k < 4; k++) {
        int i = base + k;
        if (i < N) {
            int excl = tilebase + pre[k];
            g_off[i] = excl;
            g_cur[i] = excl;
            g_dinv[i] = rsqrtf((float)(v[k] + 1));
        }
    }
}

// K6: prescale features: sfeat = dinv * feat
__global__ void k_prescale(int N) {
    int i = blockIdx.x * blockDim.x + threadIdx.x;
    if (i >= N * NPAIR) return;
    int node = i / NPAIR;
    g_sfeat[i] = g_feat[i] * g_dinv[node];
}

// K7: CSR fill (sources grouped by destination)
__global__ void k_fill(const int* __restrict__ ei, int E, int N) {
    int e = blockIdx.x * blockDim.x + threadIdx.x;
    if (e >= E) return;
    unsigned s = (unsigned)ei[e];
    unsigned d = (unsigned)ei[E + e];
    if (s < (unsigned)N && d < (unsigned)N) {
        int pos = atomicAdd(&g_cur[d], 1);
        g_srcidx[pos] = (int)s;
    }
}

// K8: warp-per-node gather + relu. Lanes 0..27 each own one feature.
__global__ void k_gather(int N) {
    int gw = (blockIdx.x * blockDim.x + threadIdx.x) >> 5;
    int lane = threadIdx.x & 31;
    if (gw >= N) return;
    int off = g_off[gw];
    int cnt = g_cnt[gw];
    float di = g_dinv[gw];
    int fl = (lane < NPAIR) ? lane : 0;
    float acc = g_sfeat[(size_t)gw * NPAIR + fl];     // self-loop term (di*feat)
    int i = 0;
    for (; i + 2 <= cnt; i += 2) {
        int s0 = g_srcidx[off + i];
        int s1 = g_srcidx[off + i + 1];
        float f0 = g_sfeat[(size_t)s0 * NPAIR + fl];
        float f1 = g_sfeat[(size_t)s1 * NPAIR + fl];
        acc += f0 + f1;
    }
    if (i < cnt)
        acc += g_sfeat[(size_t)g_srcidx[off + i] * NPAIR + fl];
    if (lane < NPAIR)
        g_agg[(size_t)gw * NPAIR + lane] = fmaxf(di * acc, 0.f);
}

// K9: gram partials: block b writes g_Gpart[e*GRAMB + b]
__global__ void k_gram(int N) {
    __shared__ float sy[32 * 29];
    float acc[4] = {0.f, 0.f, 0.f, 0.f};
    int tid = threadIdx.x;
    int ntiles = (N + 31) / 32;
    for (int tb = blockIdx.x; tb < ntiles; tb += gridDim.x) {
        int base = tb * 32;
        __syncthreads();
        for (int idx = tid; idx < 32 * NPAIR; idx += blockDim.x) {
            int nn = idx / NPAIR, f = idx - nn * NPAIR;
            float v = 0.f;
            if (base + nn < N) v = g_agg[(size_t)(base + nn) * NPAIR + f];
            sy[nn * 29 + f] = v;
        }
        __syncthreads();
#pragma unroll
        for (int k = 0; k < 4; k++) {
            int e = tid + k * 256;
            if (e < 784) {
                int i = e / 28, j = e - i * 28;
                float a = 0.f;
#pragma unroll
                for (int nn = 0; nn < 32; nn++)
                    a += sy[nn * 29 + i] * sy[nn * 29 + j];
                acc[k] += a;
            }
        }
    }
#pragma unroll
    for (int k = 0; k < 4; k++) {
        int e = tid + k * 256;
        if (e < 784) g_Gpart[e * GRAMB + blockIdx.x] = acc[k];
    }
}

// K10: reduce gram partials
__global__ void k_gred() {
    int e = blockIdx.x * blockDim.x + threadIdx.x;
    if (e >= 784) return;
    float s = 0.f;
    for (int b = 0; b < GRAMB; b++) s += g_Gpart[e * GRAMB + b];
    g_G[e] = s;
}

// K11: tiny MLP head, single block of 128 threads
__global__ void k_mlp(const float* __restrict__ W1, const float* __restrict__ b1,
                      const float* __restrict__ W2, const float* __restrict__ b2,
                      float* __restrict__ out) {
    __shared__ float sg[784];
    __shared__ float sh[128];
    int t = threadIdx.x;
    for (int i = t; i < 784; i += 128) sg[i] = g_G[i];
    __syncthreads();
    const float* w = W1 + (size_t)t * 784;
    float h = b1[t];
    for (int j = 0; j < 784; j++) h += w[j] * sg[j];
    h = fmaxf(h, 0.f);
    sh[t] = h * W2[t];
    __syncthreads();
    for (int off = 64; off; off >>= 1) {
        if (t < off) sh[t] += sh[t + off];
        __syncthreads();
    }
    if (t == 0) {
        float z = sh[0] + b2[0];
        out[0] = 1.f / (1.f + expf(-z));
    }
}

extern "C" void kernel_launch(void* const* d_in, const int* in_sizes, int n_in,
                              void* d_out, int out_size) {
    const float* x  = (const float*)d_in[0];
    const int*   ei = (const int*)d_in[1];     // int32 (JAX x64 disabled)
    const float* qw = (const float*)d_in[2];
    const float* W1 = (const float*)d_in[3];
    const float* b1 = (const float*)d_in[4];
    const float* W2 = (const float*)d_in[5];
    const float* b2 = (const float*)d_in[6];
    int N = in_sizes[0] / NF;
    int E = in_sizes[1] / 2;
    int ntiles = (N + TILE - 1) / TILE;

    k_setup   <<<1, 32>>>(qw);
    k_feat    <<<(N + 7) / 8, 256>>>(x, N);
    k_zero    <<<(N + 255) / 256, 256>>>(N);
    k_hist    <<<(E + 255) / 256, 256>>>(ei + E, E, N);
    k_scanA   <<<ntiles, 1024>>>(N);
    k_scanB   <<<1, 32>>>(ntiles);
    k_scanC   <<<ntiles, 1024>>>(N);
    k_prescale<<<(N * NPAIR + 255) / 256, 256>>>(N);
    k_fill    <<<(E + 255) / 256, 256>>>(ei, E, N);
    k_gather  <<<(N + 7) / 8, 256>>>(N);
    k_gram    <<<GRAMB, 256>>>(N);
    k_gred    <<<4, 256>>>();
    k_mlp     <<<1, 128>>>(W1, b1, W2, b2, (float*)d_out);
}

// round 4
// speedup vs baseline: 1.0364x; 1.0364x over previous
#include <cuda_runtime.h>
#include <math.h>

#define NQ 8
#define NF 256
#define NPAIR 28
#define STRIDE 32
#define MAXN 50176
#define MAXE 1600000
#define TILE 4096
#define GRAMB 148

// ---------------- static scratch ----------------
__device__ float g_sfeat[MAXN * STRIDE];  // dinv-scaled features, padded rows
__device__ float g_agg  [MAXN * STRIDE];  // relu(aggregated), padded rows
__device__ int   g_cnt [MAXN];
__device__ int   g_off [MAXN];
__device__ int   g_cur [MAXN];
__device__ int   g_srcidx[MAXE];
__device__ float g_dinv[MAXN];
__device__ float g_coefs[NPAIR * 4];      // (B00, -B00, 2ReB01, pad)
__device__ int   g_tsum[32];
__device__ float g_G[784];

__constant__ int c_pair_a[NPAIR] = {
    0,0,0,0,0,0,0, 1,1,1,1,1,1, 2,2,2,2,2, 3,3,3,3, 4,4,4, 5,5, 6
};

// ---------------- complex 2x2 helpers ----------------
__device__ __forceinline__ float2 cmul(float2 a, float2 b) {
    return make_float2(a.x * b.x - a.y * b.y, a.x * b.y + a.y * b.x);
}
__device__ __forceinline__ float2 cadd(float2 a, float2 b) {
    return make_float2(a.x + b.x, a.y + b.y);
}
__device__ __forceinline__ void mm2(const float2* A, const float2* B, float2* C) {
#pragma unroll
    for (int i = 0; i < 2; i++)
#pragma unroll
        for (int j = 0; j < 2; j++)
            C[i * 2 + j] = cadd(cmul(A[i * 2 + 0], B[0 * 2 + j]),
                                cmul(A[i * 2 + 1], B[1 * 2 + j]));
}

// K1: coefficients + zero cnt + zero G
__global__ void k_setup(const float* __restrict__ qw, int N) {
    int g = blockIdx.x * blockDim.x + threadIdx.x;
    if (g < N) g_cnt[g] = 0;
    if (g < 784) g_G[g] = 0.f;
    if (g >= NPAIR) return;
    int t = g;
    const float* p = qw + 6 * t;
    float2 M[4], T[4], R[4];
    float c, s;
    c = cosf(0.5f * p[0]); s = sinf(0.5f * p[0]);
    M[0] = make_float2(c, 0); M[1] = make_float2(0, -s);
    M[2] = make_float2(0, -s); M[3] = make_float2(c, 0);            // Rx(p0)
    c = cosf(0.5f * p[1]); s = sinf(0.5f * p[1]);
    R[0] = make_float2(c, 0); R[1] = make_float2(-s, 0);
    R[2] = make_float2(s, 0); R[3] = make_float2(c, 0);
    mm2(R, M, T);                                                   // Ry(p1)·
    c = cosf(0.5f * p[2]); s = sinf(0.5f * p[2]);
    R[0] = make_float2(c, -s); R[1] = make_float2(0, 0);
    R[2] = make_float2(0, 0);  R[3] = make_float2(c, s);
    mm2(R, T, M);                                                   // Rz(p2)·
    c = cosf(0.5f * p[3]); s = sinf(0.5f * p[3]);
    R[0] = make_float2(c, 0); R[1] = make_float2(0, -s);
    R[2] = make_float2(0, -s); R[3] = make_float2(c, 0);
    mm2(R, M, T);                                                   // Rx(p3)·
    c = cosf(0.5f * p[4]); s = sinf(0.5f * p[4]);
    R[0] = make_float2(c, 0); R[1] = make_float2(-s, 0);
    R[2] = make_float2(s, 0); R[3] = make_float2(c, 0);
    mm2(R, T, M);                                                   // Ry(p4)·
    c = cosf(0.5f * p[5]); s = sinf(0.5f * p[5]);
    R[0] = make_float2(c, -s); R[1] = make_float2(0, 0);
    R[2] = make_float2(0, 0);  R[3] = make_float2(c, s);
    mm2(R, M, T);                                                   // T = A
    float b00 = T[0].x * T[0].x + T[0].y * T[0].y
              - (T[2].x * T[2].x + T[2].y * T[2].y);
    float b01x2 = 2.f * (T[0].x * T[1].x + T[0].y * T[1].y
                       - T[2].x * T[3].x - T[2].y * T[3].y);
    g_coefs[t * 4 + 0] = b00;
    g_coefs[t * 4 + 1] = -b00;
    g_coefs[t * 4 + 2] = b01x2;
}

// K2: in-degree histogram, 4 edges/thread via int4
__global__ void k_hist(const int4* __restrict__ dst4, int E4, int N) {
    int t = blockIdx.x * blockDim.x + threadIdx.x;
    if (t >= E4) return;
    int4 d = dst4[t];
    if ((unsigned)d.x < (unsigned)N) atomicAdd(&g_cnt[d.x], 1);
    if ((unsigned)d.y < (unsigned)N) atomicAdd(&g_cnt[d.y], 1);
    if ((unsigned)d.z < (unsigned)N) atomicAdd(&g_cnt[d.z], 1);
    if ((unsigned)d.w < (unsigned)N) atomicAdd(&g_cnt[d.w], 1);
}

// K3: per-tile sums
__global__ void k_scanA(int N) {
    __shared__ int sred[32];
    int b = blockIdx.x, t = threadIdx.x;
    int lane = t & 31, warp = t >> 5;
    int base = b * TILE + t * 4;
    int s = 0;
#pragma unroll
    for (int k = 0; k < 4; k++) {
        int i = base + k;
        s += (i < N) ? g_cnt[i] : 0;
    }
#pragma unroll
    for (int off = 16; off; off >>= 1) s += __shfl_xor_sync(~0u, s, off);
    if (lane == 0) sred[warp] = s;
    __syncthreads();
    if (warp == 0) {
        int v = sred[lane];
#pragma unroll
        for (int off = 16; off; off >>= 1) v += __shfl_xor_sync(~0u, v, off);
        if (lane == 0) g_tsum[b] = v;
    }
}

// K4: apply scan (tile prefix computed inline) -> off, cur, dinv
__global__ void k_scanC(int N, int ntiles) {
    __shared__ int swsum[32];
    __shared__ int swpre[32];
    __shared__ int s_tb;
    int b = blockIdx.x, t = threadIdx.x;
    int lane = t & 31, warp = t >> 5;
    if (t < 32) {                 // tile-level exclusive prefix (ntiles <= 32)
        int v = (t < ntiles) ? g_tsum[t] : 0;
        int incl = v;
#pragma unroll
        for (int off = 1; off < 32; off <<= 1) {
            int u = __shfl_up_sync(~0u, incl, off);
            if (t >= off) incl += u;
        }
        if (t == b) s_tb = incl - v;
    }
    int base = b * TILE + t * 4;
    int v[4], pre[4];
    int run = 0;
#pragma unroll
    for (int k = 0; k < 4; k++) {
        int i = base + k;
        v[k] = (i < N) ? g_cnt[i] : 0;
        pre[k] = run;
        run += v[k];
    }
    int incl = run;
#pragma unroll
    for (int off = 1; off < 32; off <<= 1) {
        int u = __shfl_up_sync(~0u, incl, off);
        if (lane >= off) incl += u;
    }
    if (lane == 31) swsum[warp] = incl;
    int texcl = incl - run;
    __syncthreads();
    if (warp == 0) {
        int w = swsum[lane];
        int wi = w;
#pragma unroll
        for (int off = 1; off < 32; off <<= 1) {
            int u = __shfl_up_sync(~0u, wi, off);
            if (lane >= off) wi += u;
        }
        swpre[lane] = wi - w;
    }
    __syncthreads();
    int tilebase = s_tb + swpre[warp] + texcl;
#pragma unroll
    for (int k = 0; k < 4; k++) {
        int i = base + k;
        if (i < N) {
            int excl = tilebase + pre[k];
            g_off[i] = excl;
            g_cur[i] = excl;
            g_dinv[i] = rsqrtf((float)(v[k] + 1));
        }
    }
}

// K5: per-node moments -> 28 features, pre-scaled by dinv. One warp per node.
__global__ void k_feat(const float* __restrict__ x, int N) {
    __shared__ float sx[8 * NF];
    int warp = threadIdx.x >> 5;
    int lane = threadIdx.x & 31;
    int node = blockIdx.x * 8 + warp;
    if (node >= N) return;                      // warp-uniform exit
    float* row = sx + warp * NF;
    const float4* x4 = (const float4*)(x + (size_t)node * NF);
    float4* r4 = (float4*)row;
    r4[lane]      = x4[lane];
    r4[lane + 32] = x4[lane + 32];
    __syncwarp();

    float ss = 0.f;
    float sm[8] = {0, 0, 0, 0, 0, 0, 0, 0};
    float Tq[8] = {0, 0, 0, 0, 0, 0, 0, 0};
#pragma unroll
    for (int k = 0; k < 8; k++) {
        int i = lane + 32 * k;
        float v = row[i];
        float v2 = v * v;
        ss += v2;
#pragma unroll
        for (int q = 0; q < 8; q++)
            sm[q] += ((i >> (7 - q)) & 1) ? -v2 : v2;
    }
#pragma unroll
    for (int q = 0; q < 8; q++) {
        const int pos = 7 - q;
#pragma unroll
        for (int t = 0; t < 4; t++) {
            int idx = lane + 32 * t;
            int i = ((idx >> pos) << (pos + 1)) | (idx & ((1 << pos) - 1));
            Tq[q] += row[i] * row[i + (1 << pos)];
        }
    }
#pragma unroll
    for (int off = 16; off; off >>= 1) {
        ss += __shfl_xor_sync(0xffffffffu, ss, off);
#pragma unroll
        for (int q = 0; q < 8; q++) {
            sm[q] += __shfl_xor_sync(0xffffffffu, sm[q], off);
            Tq[q] += __shfl_xor_sync(0xffffffffu, Tq[q], off);
        }
    }
    float outv = 0.f;
    if (lane < NPAIR) {
        int a = c_pair_a[lane];
        float S = 0.f, Tv = 0.f;
#pragma unroll
        for (int q = 0; q < 8; q++)
            if (a == q) { S = sm[q]; Tv = Tq[q]; }
        float S0 = 0.5f * (ss + S);
        float S1 = ss - S0;
        float e = (g_coefs[lane * 4 + 0] * S0 + g_coefs[lane * 4 + 1] * S1
                 + g_coefs[lane * 4 + 2] * Tv) / ss;
        outv = (0.5f + 0.5f * e) * g_dinv[node];
    }
    g_sfeat[(size_t)node * STRIDE + lane] = outv;   // lanes 28-31 write 0
}

// K6: CSR fill, 4 edges/thread
__global__ void k_fill(const int4* __restrict__ src4,
                       const int4* __restrict__ dst4, int E4, int N) {
    int t = blockIdx.x * blockDim.x + threadIdx.x;
    if (t >= E4) return;
    int4 s = src4[t];
    int4 d = dst4[t];
    if ((unsigned)d.x < (unsigned)N) g_srcidx[atomicAdd(&g_cur[d.x], 1)] = s.x;
    if ((unsigned)d.y < (unsigned)N) g_srcidx[atomicAdd(&g_cur[d.y], 1)] = s.y;
    if ((unsigned)d.z < (unsigned)N) g_srcidx[atomicAdd(&g_cur[d.z], 1)] = s.z;
    if ((unsigned)d.w < (unsigned)N) g_srcidx[atomicAdd(&g_cur[d.w], 1)] = s.w;
}

// K7: warp-per-node gather + relu, 4-way unrolled
__global__ void k_gather(int N) {
    int gw = (blockIdx.x * blockDim.x + threadIdx.x) >> 5;
    int lane = threadIdx.x & 31;
    if (gw >= N) return;
    int off = g_off[gw];
    int cnt = g_cnt[gw];
    float di = g_dinv[gw];
    float acc = g_sfeat[(size_t)gw * STRIDE + lane];  // self loop (dinv*feat)
    int i = 0;
    for (; i + 4 <= cnt; i += 4) {
        int s0 = g_srcidx[off + i];
        int s1 = g_srcidx[off + i + 1];
        int s2 = g_srcidx[off + i + 2];
        int s3 = g_srcidx[off + i + 3];
        float f0 = g_sfeat[(size_t)s0 * STRIDE + lane];
        float f1 = g_sfeat[(size_t)s1 * STRIDE + lane];
        float f2 = g_sfeat[(size_t)s2 * STRIDE + lane];
        float f3 = g_sfeat[(size_t)s3 * STRIDE + lane];
        acc += (f0 + f1) + (f2 + f3);
    }
    for (; i < cnt; i++)
        acc += g_sfeat[(size_t)g_srcidx[off + i] * STRIDE + lane];
    if (lane < NPAIR)
        g_agg[(size_t)gw * STRIDE + lane] = fmaxf(di * acc, 0.f);
}

// K8: gram partial per block, atomic merge into g_G
__global__ void k_gram(int N) {
    __shared__ float sy[32 * 29];
    float acc[4] = {0.f, 0.f, 0.f, 0.f};
    int tid = threadIdx.x;
    int ntiles = (N + 31) / 32;
    for (int tb = blockIdx.x; tb < ntiles; tb += gridDim.x) {
        int base = tb * 32;
        __syncthreads();
        for (int idx = tid; idx < 32 * NPAIR; idx += blockDim.x) {
            int nn = idx / NPAIR, f = idx - nn * NPAIR;
            float v = 0.f;
            if (base + nn < N) v = g_agg[(size_t)(base + nn) * STRIDE + f];
            sy[nn * 29 + f] = v;
        }
        __syncthreads();
#pragma unroll
        for (int k = 0; k < 4; k++) {
            int e = tid + k * 256;
            if (e < 784) {
                int i = e / 28, j = e - i * 28;
                float a = 0.f;
#pragma unroll
                for (int nn = 0; nn < 32; nn++)
                    a += sy[nn * 29 + i] * sy[nn * 29 + j];
                acc[k] += a;
            }
        }
    }
#pragma unroll
    for (int k = 0; k < 4; k++) {
        int e = tid + k * 256;
        if (e < 784) atomicAdd(&g_G[e], acc[k]);
    }
}

// K9: MLP head
__global__ void k_mlp(const float* __restrict__ W1, const float* __restrict__ b1,
                      const float* __restrict__ W2, const float* __restrict__ b2,
                      float* __restrict__ out) {
    __shared__ float sg[784];
    __shared__ float sh[128];
    int t = threadIdx.x;
    for (int i = t; i < 784; i += 128) sg[i] = g_G[i];
    __syncthreads();
    const float* w = W1 + (size_t)t * 784;
    float h = b1[t];
    for (int j = 0; j < 784; j++) h += w[j] * sg[j];
    h = fmaxf(h, 0.f);
    sh[t] = h * W2[t];
    __syncthreads();
    for (int off = 64; off; off >>= 1) {
        if (t < off) sh[t] += sh[t + off];
        __syncthreads();
    }
    if (t == 0) {
        float z = sh[0] + b2[0];
        out[0] = 1.f / (1.f + expf(-z));
    }
}

extern "C" void kernel_launch(void* const* d_in, const int* in_sizes, int n_in,
                              void* d_out, int out_size) {
    const float* x  = (const float*)d_in[0];
    const int*   ei = (const int*)d_in[1];     // int32 (JAX x64 disabled)
    const float* qw = (const float*)d_in[2];
    const float* W1 = (const float*)d_in[3];
    const float* b1 = (const float*)d_in[4];
    const float* W2 = (const float*)d_in[5];
    const float* b2 = (const float*)d_in[6];
    int N = in_sizes[0] / NF;
    int E = in_sizes[1] / 2;
    int E4 = E / 4;                              // E = 1.6M, divisible by 4
    int ntiles = (N + TILE - 1) / TILE;

    k_setup <<<(N + 255) / 256, 256>>>(qw, N);
    k_hist  <<<(E4 + 255) / 256, 256>>>((const int4*)(ei + E), E4, N);
    k_scanA <<<ntiles, 1024>>>(N);
    k_scanC <<<ntiles, 1024>>>(N, ntiles);
    k_feat  <<<(N + 7) / 8, 256>>>(x, N);
    k_fill  <<<(E4 + 255) / 256, 256>>>((const int4*)ei, (const int4*)(ei + E), E4, N);
    k_gather<<<(N + 7) / 8, 256>>>(N);
    k_gram  <<<GRAMB, 256>>>(N);
    k_mlp   <<<1, 128>>>(W1, b1, W2, b2, (float*)d_out);
}

// round 7
// speedup vs baseline: 1.3377x; 1.2907x over previous
#include <cuda_runtime.h>
#include <math.h>

#define NQ 8
#define NF 256
#define NPAIR 28
#define STRIDE 32
#define MAXN 50176
#define MAXE 1600000
#define TILE 4096

// ---------------- static scratch ----------------
__device__ float g_sfeat[MAXN * STRIDE];  // dinv-scaled features, padded rows
__device__ int   g_cnt [MAXN];
__device__ int   g_off [MAXN];
__device__ int   g_cur [MAXN];
__device__ int   g_srcidx[MAXE];
__device__ float g_dinv[MAXN];
__device__ float g_coefs[NPAIR * 4];      // (B00, -B00, 2ReB01, pad)
__device__ float g_G[784];
__device__ int   g_tick;

__constant__ int c_pair_a[NPAIR] = {
    0,0,0,0,0,0,0, 1,1,1,1,1,1, 2,2,2,2,2, 3,3,3,3, 4,4,4, 5,5, 6
};

// ---------------- complex 2x2 helpers ----------------
__device__ __forceinline__ float2 cmul(float2 a, float2 b) {
    return make_float2(a.x * b.x - a.y * b.y, a.x * b.y + a.y * b.x);
}
__device__ __forceinline__ float2 cadd(float2 a, float2 b) {
    return make_float2(a.x + b.x, a.y + b.y);
}
__device__ __forceinline__ void mm2(const float2* A, const float2* B, float2* C) {
#pragma unroll
    for (int i = 0; i < 2; i++)
#pragma unroll
        for (int j = 0; j < 2; j++)
            C[i * 2 + j] = cadd(cmul(A[i * 2 + 0], B[0 * 2 + j]),
                                cmul(A[i * 2 + 1], B[1 * 2 + j]));
}

// K1: coefficients + zero cnt/G/tick
__global__ void k_setup(const float* __restrict__ qw, int N) {
    int g = blockIdx.x * blockDim.x + threadIdx.x;
    if (g < N) g_cnt[g] = 0;
    if (g < 784) g_G[g] = 0.f;
    if (g == 800) g_tick = 0;
    if (g >= NPAIR) return;
    const float* p = qw + 6 * g;
    float2 M[4], T[4], R[4];
    float c, s;
    c = cosf(0.5f * p[0]); s = sinf(0.5f * p[0]);
    M[0] = make_float2(c, 0); M[1] = make_float2(0, -s);
    M[2] = make_float2(0, -s); M[3] = make_float2(c, 0);            // Rx(p0)
    c = cosf(0.5f * p[1]); s = sinf(0.5f * p[1]);
    R[0] = make_float2(c, 0); R[1] = make_float2(-s, 0);
    R[2] = make_float2(s, 0); R[3] = make_float2(c, 0);
    mm2(R, M, T);                                                   // Ry(p1)
    c = cosf(0.5f * p[2]); s = sinf(0.5f * p[2]);
    R[0] = make_float2(c, -s); R[1] = make_float2(0, 0);
    R[2] = make_float2(0, 0);  R[3] = make_float2(c, s);
    mm2(R, T, M);                                                   // Rz(p2)
    c = cosf(0.5f * p[3]); s = sinf(0.5f * p[3]);
    R[0] = make_float2(c, 0); R[1] = make_float2(0, -s);
    R[2] = make_float2(0, -s); R[3] = make_float2(c, 0);
    mm2(R, M, T);                                                   // Rx(p3)
    c = cosf(0.5f * p[4]); s = sinf(0.5f * p[4]);
    R[0] = make_float2(c, 0); R[1] = make_float2(-s, 0);
    R[2] = make_float2(s, 0); R[3] = make_float2(c, 0);
    mm2(R, T, M);                                                   // Ry(p4)
    c = cosf(0.5f * p[5]); s = sinf(0.5f * p[5]);
    R[0] = make_float2(c, -s); R[1] = make_float2(0, 0);
    R[2] = make_float2(0, 0);  R[3] = make_float2(c, s);
    mm2(R, M, T);                                                   // T = A
    float b00 = T[0].x * T[0].x + T[0].y * T[0].y
              - (T[2].x * T[2].x + T[2].y * T[2].y);
    float b01x2 = 2.f * (T[0].x * T[1].x + T[0].y * T[1].y
                       - T[2].x * T[3].x - T[2].y * T[3].y);
    g_coefs[g * 4 + 0] = b00;
    g_coefs[g * 4 + 1] = -b00;
    g_coefs[g * 4 + 2] = b01x2;
}

// K2: in-degree histogram, 4 edges/thread via int4 (+ scalar tail)
__global__ void k_hist(const int* __restrict__ dst, int E, int N) {
    int t = blockIdx.x * blockDim.x + threadIdx.x;
    int E4 = E >> 2;
    if (t < E4) {
        int4 d = ((const int4*)dst)[t];
        if ((unsigned)d.x < (unsigned)N) atomicAdd(&g_cnt[d.x], 1);
        if ((unsigned)d.y < (unsigned)N) atomicAdd(&g_cnt[d.y], 1);
        if ((unsigned)d.z < (unsigned)N) atomicAdd(&g_cnt[d.z], 1);
        if ((unsigned)d.w < (unsigned)N) atomicAdd(&g_cnt[d.w], 1);
    }
    if (t == 0)
        for (int e = E4 * 4; e < E; e++) {
            int d = dst[e];
            if ((unsigned)d < (unsigned)N) atomicAdd(&g_cnt[d], 1);
        }
}

// K3: fused scan. Each block sums its prefix tiles, then scans its own tile.
__global__ void k_scan(int N) {
    __shared__ int sred[32];
    __shared__ int swsum[32];
    __shared__ int swpre[32];
    __shared__ int s_prefix;
    int b = blockIdx.x, t = threadIdx.x;
    int lane = t & 31, warp = t >> 5;
    // prefix = sum of g_cnt[0 .. b*TILE)
    int ps = 0;
    for (int i = t; i < b * TILE; i += 1024) ps += g_cnt[i];
#pragma unroll
    for (int off = 16; off; off >>= 1) ps += __shfl_xor_sync(~0u, ps, off);
    if (lane == 0) sred[warp] = ps;
    __syncthreads();
    if (warp == 0) {
        int v = sred[lane];
#pragma unroll
        for (int off = 16; off; off >>= 1) v += __shfl_xor_sync(~0u, v, off);
        if (lane == 0) s_prefix = v;
    }
    // own tile scan
    int base = b * TILE + t * 4;
    int v[4], pre[4];
    int run = 0;
#pragma unroll
    for (int k = 0; k < 4; k++) {
        int i = base + k;
        v[k] = (i < N) ? g_cnt[i] : 0;
        pre[k] = run;
        run += v[k];
    }
    int incl = run;
#pragma unroll
    for (int off = 1; off < 32; off <<= 1) {
        int u = __shfl_up_sync(~0u, incl, off);
        if (lane >= off) incl += u;
    }
    if (lane == 31) swsum[warp] = incl;
    int texcl = incl - run;
    __syncthreads();
    if (warp == 0) {
        int w = swsum[lane];
        int wi = w;
#pragma unroll
        for (int off = 1; off < 32; off <<= 1) {
            int u = __shfl_up_sync(~0u, wi, off);
            if (lane >= off) wi += u;
        }
        swpre[lane] = wi - w;
    }
    __syncthreads();
    int tilebase = s_prefix + swpre[warp] + texcl;
#pragma unroll
    for (int k = 0; k < 4; k++) {
        int i = base + k;
        if (i < N) {
            int excl = tilebase + pre[k];
            g_off[i] = excl;
            g_cur[i] = excl;
            g_dinv[i] = rsqrtf((float)(v[k] + 1));
        }
    }
}

// K4: per-node moments -> 28 features, pre-scaled by dinv. One warp per node.
__global__ void k_feat(const float* __restrict__ x, int N) {
    __shared__ float sx[8 * NF];
    int warp = threadIdx.x >> 5;
    int lane = threadIdx.x & 31;
    int node = blockIdx.x * 8 + warp;
    if (node >= N) return;
    float* row = sx + warp * NF;
    const float4* x4 = (const float4*)(x + (size_t)node * NF);
    float4* r4 = (float4*)row;
    r4[lane]      = x4[lane];
    r4[lane + 32] = x4[lane + 32];
    __syncwarp();

    float ss = 0.f;
    float sm[8] = {0, 0, 0, 0, 0, 0, 0, 0};
    float Tq[8] = {0, 0, 0, 0, 0, 0, 0, 0};
#pragma unroll
    for (int k = 0; k < 8; k++) {
        int i = lane + 32 * k;
        float v = row[i];
        float v2 = v * v;
        ss += v2;
#pragma unroll
        for (int q = 0; q < 8; q++)
            sm[q] += ((i >> (7 - q)) & 1) ? -v2 : v2;
    }
#pragma unroll
    for (int q = 0; q < 8; q++) {
        const int pos = 7 - q;
#pragma unroll
        for (int t = 0; t < 4; t++) {
            int idx = lane + 32 * t;
            int i = ((idx >> pos) << (pos + 1)) | (idx & ((1 << pos) - 1));
            Tq[q] += row[i] * row[i + (1 << pos)];
        }
    }
#pragma unroll
    for (int off = 16; off; off >>= 1) {
        ss += __shfl_xor_sync(0xffffffffu, ss, off);
#pragma unroll
        for (int q = 0; q < 8; q++) {
            sm[q] += __shfl_xor_sync(0xffffffffu, sm[q], off);
            Tq[q] += __shfl_xor_sync(0xffffffffu, Tq[q], off);
        }
    }
    float outv = 0.f;
    if (lane < NPAIR) {
        int a = c_pair_a[lane];
        float S = 0.f, Tv = 0.f;
#pragma unroll
        for (int q = 0; q < 8; q++)
            if (a == q) { S = sm[q]; Tv = Tq[q]; }
        float S0 = 0.5f * (ss + S);
        float S1 = ss - S0;
        float e = (g_coefs[lane * 4 + 0] * S0 + g_coefs[lane * 4 + 1] * S1
                 + g_coefs[lane * 4 + 2] * Tv) / ss;
        outv = (0.5f + 0.5f * e) * g_dinv[node];
    }
    g_sfeat[(size_t)node * STRIDE + lane] = outv;   // lanes 28-31 write 0
}

// K5: CSR fill, 4 edges/thread (+ scalar tail)
__global__ void k_fill(const int* __restrict__ ei, int E, int N) {
    int t = blockIdx.x * blockDim.x + threadIdx.x;
    int E4 = E >> 2;
    if (t < E4) {
        int4 s = ((const int4*)ei)[t];
        int4 d = ((const int4*)(ei + E))[t];
        if ((unsigned)d.x < (unsigned)N) g_srcidx[atomicAdd(&g_cur[d.x], 1)] = s.x;
        if ((unsigned)d.y < (unsigned)N) g_srcidx[atomicAdd(&g_cur[d.y], 1)] = s.y;
        if ((unsigned)d.z < (unsigned)N) g_srcidx[atomicAdd(&g_cur[d.z], 1)] = s.z;
        if ((unsigned)d.w < (unsigned)N) g_srcidx[atomicAdd(&g_cur[d.w], 1)] = s.w;
    }
    if (t == 0)
        for (int e = E4 * 4; e < E; e++) {
            int s = ei[e], d = ei[E + e];
            if ((unsigned)d < (unsigned)N) g_srcidx[atomicAdd(&g_cur[d], 1)] = s;
        }
}

// K6: fused gather + gram + (last block) MLP.
// Block = 32 nodes (8 warps x 4 nodes). Gram partial from smem rows.
__global__ void k_gathergram(int N,
                             const float* __restrict__ W1,
                             const float* __restrict__ b1,
                             const float* __restrict__ W2,
                             const float* __restrict__ b2,
                             float* __restrict__ out) {
    __shared__ float sy[32 * 29];
    __shared__ float sg[784];
    __shared__ float swacc[8];
    __shared__ int   s_last;
    int tid = threadIdx.x;
    int warp = tid >> 5, lane = tid & 31;
    int base = blockIdx.x * 32;

    // ---- gather: each warp handles 4 nodes ----
#pragma unroll
    for (int k = 0; k < 4; k++) {
        int local = warp * 4 + k;
        int node = base + local;
        float r = 0.f;
        if (node < N) {
            int off = g_off[node];
            int cnt = g_cnt[node];
            float di = g_dinv[node];
            float acc = g_sfeat[(size_t)node * STRIDE + lane];  // self loop
            int i = 0;
            for (; i + 4 <= cnt; i += 4) {
                int s0 = g_srcidx[off + i];
                int s1 = g_srcidx[off + i + 1];
                int s2 = g_srcidx[off + i + 2];
                int s3 = g_srcidx[off + i + 3];
                float f0 = g_sfeat[(size_t)s0 * STRIDE + lane];
                float f1 = g_sfeat[(size_t)s1 * STRIDE + lane];
                float f2 = g_sfeat[(size_t)s2 * STRIDE + lane];
                float f3 = g_sfeat[(size_t)s3 * STRIDE + lane];
                acc += (f0 + f1) + (f2 + f3);
            }
            for (; i < cnt; i++)
                acc += g_sfeat[(size_t)g_srcidx[off + i] * STRIDE + lane];
            r = fmaxf(di * acc, 0.f);
        }
        if (lane < NPAIR) sy[local * 29 + lane] = r;
    }
    __syncthreads();

    // ---- gram partial: 784 elements over 256 threads x 4 ----
#pragma unroll
    for (int k = 0; k < 4; k++) {
        int e = tid + k * 256;
        if (e < 784) {
            int i = e / 28, j = e - i * 28;
            float a = 0.f;
#pragma unroll
            for (int nn = 0; nn < 32; nn++)
                a += sy[nn * 29 + i] * sy[nn * 29 + j];
            atomicAdd(&g_G[e], a);
        }
    }

    // ---- elect last block ----
    __threadfence();
    if (tid == 0) {
        int old = atomicAdd(&g_tick, 1);
        s_last = (old == gridDim.x - 1);
    }
    __syncthreads();
    if (!s_last) return;

    // ---- MLP (one block, coalesced W1 reads) ----
    for (int i = tid; i < 784; i += 256) sg[i] = __ldcg(&g_G[i]);
    __syncthreads();
    float wacc = 0.f;
#pragma unroll
    for (int o = 0; o < 16; o++) {
        int r = warp * 16 + o;                 // 8 warps x 16 = 128 rows
        const float* wr = W1 + (size_t)r * 784;
        float dot = 0.f;
        for (int m = lane; m < 784; m += 32) dot += wr[m] * sg[m];
#pragma unroll
        for (int off = 16; off; off >>= 1)
            dot += __shfl_xor_sync(~0u, dot, off);
        if (lane == 0) wacc += fmaxf(dot + b1[r], 0.f) * W2[r];
    }
    if (lane == 0) swacc[warp] = wacc;
    __syncthreads();
    if (tid == 0) {
        float z = b2[0];
#pragma unroll
        for (int w = 0; w < 8; w++) z += swacc[w];
        out[0] = 1.f / (1.f + expf(-z));
    }
}

extern "C" void kernel_launch(void* const* d_in, const int* in_sizes, int n_in,
                              void* d_out, int out_size) {
    const float* x  = (const float*)d_in[0];
    const int*   ei = (const int*)d_in[1];     // int32 (JAX x64 disabled)
    const float* qw = (const float*)d_in[2];
    const float* W1 = (const float*)d_in[3];
    const float* b1 = (const float*)d_in[4];
    const float* W2 = (const float*)d_in[5];
    const float* b2 = (const float*)d_in[6];
    int N = in_sizes[0] / NF;
    int E = in_sizes[1] / 2;
    int E4 = E >> 2;
    int ntiles = (N + TILE - 1) / TILE;

    k_setup     <<<(N + 255) / 256, 256>>>(qw, N);
    k_hist      <<<(E4 + 255) / 256, 256>>>(ei + E, E, N);
    k_scan      <<<ntiles, 1024>>>(N);
    k_feat      <<<(N + 7) / 8, 256>>>(x, N);
    k_fill      <<<(E4 + 255) / 256, 256>>>(ei, E, N);
    k_gathergram<<<(N + 31) / 32, 256>>>(N, W1, b1, W2, b2, (float*)d_out);
}

// round 8
// speedup vs baseline: 1.4712x; 1.0998x over previous
#include <cuda_runtime.h>
#include <math.h>

#define NQ 8
#define NF 256
#define NPAIR 28
#define STRIDE 32
#define MAXN 50176
#define MAXE 1600000
#define TILE 4096

// ---------------- static scratch ----------------
__device__ float g_sfeat[MAXN * STRIDE];  // dinv-scaled features, padded rows
__device__ int   g_cnt [MAXN];
__device__ int   g_off [MAXN];
__device__ int   g_cur [MAXN];
__device__ int   g_srcidx[MAXE];
__device__ float g_dinv[MAXN];
__device__ float g_coefs[NPAIR * 4];      // (B00, -B00, 2ReB01, pad)
__device__ float g_G[784];
__device__ int   g_tick;

// ---------------- complex 2x2 helpers ----------------
__device__ __forceinline__ float2 cmul(float2 a, float2 b) {
    return make_float2(a.x * b.x - a.y * b.y, a.x * b.y + a.y * b.x);
}
__device__ __forceinline__ float2 cadd(float2 a, float2 b) {
    return make_float2(a.x + b.x, a.y + b.y);
}
__device__ __forceinline__ void mm2(const float2* A, const float2* B, float2* C) {
#pragma unroll
    for (int i = 0; i < 2; i++)
#pragma unroll
        for (int j = 0; j < 2; j++)
            C[i * 2 + j] = cadd(cmul(A[i * 2 + 0], B[0 * 2 + j]),
                                cmul(A[i * 2 + 1], B[1 * 2 + j]));
}

__device__ __forceinline__ float dot4(float4 a, float4 b) {
    return a.x * b.x + a.y * b.y + a.z * b.z + a.w * b.w;
}

// 'a' (first qubit) of pair f in combinations(range(8),2) order, as ALU chain
__device__ __forceinline__ int pair_a(int f) {
    return (f < 7) ? 0 : (f < 13) ? 1 : (f < 18) ? 2 : (f < 22) ? 3
         : (f < 25) ? 4 : (f < 27) ? 5 : 6;
}

// K1: coefficients + zero cnt/G/tick
__global__ void k_setup(const float* __restrict__ qw, int N) {
    int g = blockIdx.x * blockDim.x + threadIdx.x;
    if (g < N) g_cnt[g] = 0;
    if (g < 784) g_G[g] = 0.f;
    if (g == 800) g_tick = 0;
    if (g >= NPAIR) return;
    const float* p = qw + 6 * g;
    float2 M[4], T[4], R[4];
    float c, s;
    c = cosf(0.5f * p[0]); s = sinf(0.5f * p[0]);
    M[0] = make_float2(c, 0); M[1] = make_float2(0, -s);
    M[2] = make_float2(0, -s); M[3] = make_float2(c, 0);            // Rx(p0)
    c = cosf(0.5f * p[1]); s = sinf(0.5f * p[1]);
    R[0] = make_float2(c, 0); R[1] = make_float2(-s, 0);
    R[2] = make_float2(s, 0); R[3] = make_float2(c, 0);
    mm2(R, M, T);                                                   // Ry(p1)
    c = cosf(0.5f * p[2]); s = sinf(0.5f * p[2]);
    R[0] = make_float2(c, -s); R[1] = make_float2(0, 0);
    R[2] = make_float2(0, 0);  R[3] = make_float2(c, s);
    mm2(R, T, M);                                                   // Rz(p2)
    c = cosf(0.5f * p[3]); s = sinf(0.5f * p[3]);
    R[0] = make_float2(c, 0); R[1] = make_float2(0, -s);
    R[2] = make_float2(0, -s); R[3] = make_float2(c, 0);
    mm2(R, M, T);                                                   // Rx(p3)
    c = cosf(0.5f * p[4]); s = sinf(0.5f * p[4]);
    R[0] = make_float2(c, 0); R[1] = make_float2(-s, 0);
    R[2] = make_float2(s, 0); R[3] = make_float2(c, 0);
    mm2(R, T, M);                                                   // Ry(p4)
    c = cosf(0.5f * p[5]); s = sinf(0.5f * p[5]);
    R[0] = make_float2(c, -s); R[1] = make_float2(0, 0);
    R[2] = make_float2(0, 0);  R[3] = make_float2(c, s);
    mm2(R, M, T);                                                   // T = A
    float b00 = T[0].x * T[0].x + T[0].y * T[0].y
              - (T[2].x * T[2].x + T[2].y * T[2].y);
    float b01x2 = 2.f * (T[0].x * T[1].x + T[0].y * T[1].y
                       - T[2].x * T[3].x - T[2].y * T[3].y);
    g_coefs[g * 4 + 0] = b00;
    g_coefs[g * 4 + 1] = -b00;
    g_coefs[g * 4 + 2] = b01x2;
}

// K2: in-degree histogram, 4 edges/thread via int4 (+ scalar tail)
__global__ void k_hist(const int* __restrict__ dst, int E, int N) {
    int t = blockIdx.x * blockDim.x + threadIdx.x;
    int E4 = E >> 2;
    if (t < E4) {
        int4 d = ((const int4*)dst)[t];
        if ((unsigned)d.x < (unsigned)N) atomicAdd(&g_cnt[d.x], 1);
        if ((unsigned)d.y < (unsigned)N) atomicAdd(&g_cnt[d.y], 1);
        if ((unsigned)d.z < (unsigned)N) atomicAdd(&g_cnt[d.z], 1);
        if ((unsigned)d.w < (unsigned)N) atomicAdd(&g_cnt[d.w], 1);
    }
    if (t == 0)
        for (int e = E4 * 4; e < E; e++) {
            int d = dst[e];
            if ((unsigned)d < (unsigned)N) atomicAdd(&g_cnt[d], 1);
        }
}

// K3: fused scan. Each block sums its prefix tiles, then scans its own tile.
__global__ void k_scan(int N) {
    __shared__ int sred[32];
    __shared__ int swsum[32];
    __shared__ int swpre[32];
    __shared__ int s_prefix;
    int b = blockIdx.x, t = threadIdx.x;
    int lane = t & 31, warp = t >> 5;
    int ps = 0;
    for (int i = t; i < b * TILE; i += 1024) ps += g_cnt[i];
#pragma unroll
    for (int off = 16; off; off >>= 1) ps += __shfl_xor_sync(~0u, ps, off);
    if (lane == 0) sred[warp] = ps;
    __syncthreads();
    if (warp == 0) {
        int v = sred[lane];
#pragma unroll
        for (int off = 16; off; off >>= 1) v += __shfl_xor_sync(~0u, v, off);
        if (lane == 0) s_prefix = v;
    }
    int base = b * TILE + t * 4;
    int v[4], pre[4];
    int run = 0;
#pragma unroll
    for (int k = 0; k < 4; k++) {
        int i = base + k;
        v[k] = (i < N) ? g_cnt[i] : 0;
        pre[k] = run;
        run += v[k];
    }
    int incl = run;
#pragma unroll
    for (int off = 1; off < 32; off <<= 1) {
        int u = __shfl_up_sync(~0u, incl, off);
        if (lane >= off) incl += u;
    }
    if (lane == 31) swsum[warp] = incl;
    int texcl = incl - run;
    __syncthreads();
    if (warp == 0) {
        int w = swsum[lane];
        int wi = w;
#pragma unroll
        for (int off = 1; off < 32; off <<= 1) {
            int u = __shfl_up_sync(~0u, wi, off);
            if (lane >= off) wi += u;
        }
        swpre[lane] = wi - w;
    }
    __syncthreads();
    int tilebase = s_prefix + swpre[warp] + texcl;
#pragma unroll
    for (int k = 0; k < 4; k++) {
        int i = base + k;
        if (i < N) {
            int excl = tilebase + pre[k];
            g_off[i] = excl;
            g_cur[i] = excl;
            g_dinv[i] = rsqrtf((float)(v[k] + 1));
        }
    }
}

// K4: features. 4 nodes/warp, 8 lanes/node, 32 values/lane in registers.
// i = seg(3b)*32 + g(3b)*4 + j(2b);  qubit q -> bit (7-q) of i.
__global__ void k_feat(const float* __restrict__ x, int N) {
    __shared__ float4 smw[8][256];    // per warp: [sub*64 + seg*8 + g]
    int lane = threadIdx.x & 31;
    int warp = threadIdx.x >> 5;
    int g    = lane & 7;
    int sub  = lane >> 3;
    int node = blockIdx.x * 32 + warp * 4 + sub;
    int nclamp = node < N ? node : N - 1;

    const float4* xr = (const float4*)(x + (size_t)nclamp * NF);
    float4 v[8];
#pragma unroll
    for (int sg = 0; sg < 8; sg++) v[sg] = xr[sg * 8 + g];

    float4* sw = &smw[warp][sub * 64];
#pragma unroll
    for (int sg = 0; sg < 8; sg++) sw[sg * 8 + g] = v[sg];
    __syncwarp();

    // in-register partials
    float s2 = 0.f, p0 = 0.f, p1 = 0.f, p2 = 0.f, p6 = 0.f, t6 = 0.f;
#pragma unroll
    for (int sg = 0; sg < 8; sg++) {
        float4 a = v[sg];
        float nn = dot4(a, a);
        s2 += nn;
        p0 += (sg & 4) ? -nn : nn;
        p1 += (sg & 2) ? -nn : nn;
        p2 += (sg & 1) ? -nn : nn;
        p6 += a.x * a.x + a.y * a.y - a.z * a.z - a.w * a.w;
        t6 += a.x * a.z + a.y * a.w;
    }
    float t0 = dot4(v[0], v[4]) + dot4(v[1], v[5])
             + dot4(v[2], v[6]) + dot4(v[3], v[7]);
    float t1 = dot4(v[0], v[2]) + dot4(v[1], v[3])
             + dot4(v[4], v[6]) + dot4(v[5], v[7]);
    float t2 = dot4(v[0], v[1]) + dot4(v[2], v[3])
             + dot4(v[4], v[5]) + dot4(v[6], v[7]);

    // cross-lane partials (double-count -> halve after reduce)
    float t3 = 0.f, t4 = 0.f, t5 = 0.f;
#pragma unroll
    for (int sg = 0; sg < 8; sg++) t3 += dot4(v[sg], sw[sg * 8 + (g ^ 4)]);
#pragma unroll
    for (int sg = 0; sg < 8; sg++) t4 += dot4(v[sg], sw[sg * 8 + (g ^ 2)]);
#pragma unroll
    for (int sg = 0; sg < 8; sg++) t5 += dot4(v[sg], sw[sg * 8 + (g ^ 1)]);

    // 8-lane plain butterflies (masks 1,2,4 stay in subgroup)
#define RED8(a) { a += __shfl_xor_sync(~0u, a, 1); \
                  a += __shfl_xor_sync(~0u, a, 2); \
                  a += __shfl_xor_sync(~0u, a, 4); }
    RED8(p0) RED8(p1) RED8(p2) RED8(p6)
    RED8(t0) RED8(t1) RED8(t2) RED8(t6)
    RED8(t3) RED8(t4) RED8(t5)
    t3 *= 0.5f; t4 *= 0.5f; t5 *= 0.5f;

    // ss + lane-signed sums of s2 via shared Walsh butterflies
    float r0  = s2 + __shfl_xor_sync(~0u, s2, 1);
    float r1  = s2 + __shfl_xor_sync(~0u, s2, 2);
    float r01 = r0 + __shfl_xor_sync(~0u, r0, 2);
    float r02 = r0 + __shfl_xor_sync(~0u, r0, 4);
    float r12 = r1 + __shfl_xor_sync(~0u, r1, 4);
    float ssr = r01 + __shfl_xor_sync(~0u, r01, 4);
    float u3  = r01 - __shfl_xor_sync(~0u, r01, 4);   // diff over g bit2
    float u4  = r02 - __shfl_xor_sync(~0u, r02, 2);   // diff over g bit1
    float u5  = r12 - __shfl_xor_sync(~0u, r12, 1);   // diff over g bit0
    float q3v = ((g >> 2) & 1) ? -u3 : u3;
    float q4v = ((g >> 1) & 1) ? -u4 : u4;
    float q5v = (g & 1) ? -u5 : u5;

    float smv[7] = {p0, p1, p2, q3v, q4v, q5v, p6};
    float tqv[7] = {t0, t1, t2, t3, t4, t5, t6};

    float di = g_dinv[nclamp];
    float inv_ss = 1.f / ssr;
#pragma unroll
    for (int k = 0; k < 4; k++) {
        int f = g + 8 * k;
        float outv = 0.f;
        if (f < NPAIR) {
            int a = pair_a(f);
            float S = 0.f, Tv = 0.f;
#pragma unroll
            for (int q = 0; q < 7; q++)
                if (a == q) { S = smv[q]; Tv = tqv[q]; }
            float S0 = 0.5f * (ssr + S);
            float S1 = ssr - S0;
            float4 co = *(const float4*)&g_coefs[f * 4];
            float e = (co.x * S0 + co.y * S1 + co.z * Tv) * inv_ss;
            outv = (0.5f + 0.5f * e) * di;
        }
        if (node < N) g_sfeat[(size_t)node * STRIDE + f] = outv;
    }
#undef RED8
}

// K5: CSR fill, 4 edges/thread (+ scalar tail)
__global__ void k_fill(const int* __restrict__ ei, int E, int N) {
    int t = blockIdx.x * blockDim.x + threadIdx.x;
    int E4 = E >> 2;
    if (t < E4) {
        int4 s = ((const int4*)ei)[t];
        int4 d = ((const int4*)(ei + E))[t];
        if ((unsigned)d.x < (unsigned)N) g_srcidx[atomicAdd(&g_cur[d.x], 1)] = s.x;
        if ((unsigned)d.y < (unsigned)N) g_srcidx[atomicAdd(&g_cur[d.y], 1)] = s.y;
        if ((unsigned)d.z < (unsigned)N) g_srcidx[atomicAdd(&g_cur[d.z], 1)] = s.z;
        if ((unsigned)d.w < (unsigned)N) g_srcidx[atomicAdd(&g_cur[d.w], 1)] = s.w;
    }
    if (t == 0)
        for (int e = E4 * 4; e < E; e++) {
            int s = ei[e], d = ei[E + e];
            if ((unsigned)d < (unsigned)N) g_srcidx[atomicAdd(&g_cur[d], 1)] = s;
        }
}

// K6: fused gather + gram + (last block) MLP.
__global__ void k_gathergram(int N,
                             const float* __restrict__ W1,
                             const float* __restrict__ b1,
                             const float* __restrict__ W2,
                             const float* __restrict__ b2,
                             float* __restrict__ out) {
    __shared__ float sy[32 * 29];
    __shared__ float sg[784];
    __shared__ float swacc[8];
    __shared__ int   s_last;
    int tid = threadIdx.x;
    int warp = tid >> 5, lane = tid & 31;
    int base = blockIdx.x * 32;

    // ---- gather: each warp handles 4 nodes ----
#pragma unroll
    for (int k = 0; k < 4; k++) {
        int local = warp * 4 + k;
        int node = base + local;
        float r = 0.f;
        if (node < N) {
            int off = g_off[node];
            int cnt = g_cnt[node];
            float di = g_dinv[node];
            float acc = g_sfeat[(size_t)node * STRIDE + lane];  // self loop
            int i = 0;
            for (; i + 4 <= cnt; i += 4) {
                int s0 = g_srcidx[off + i];
                int s1 = g_srcidx[off + i + 1];
                int s2 = g_srcidx[off + i + 2];
                int s3 = g_srcidx[off + i + 3];
                float f0 = g_sfeat[(size_t)s0 * STRIDE + lane];
                float f1 = g_sfeat[(size_t)s1 * STRIDE + lane];
                float f2 = g_sfeat[(size_t)s2 * STRIDE + lane];
                float f3 = g_sfeat[(size_t)s3 * STRIDE + lane];
                acc += (f0 + f1) + (f2 + f3);
            }
            for (; i < cnt; i++)
                acc += g_sfeat[(size_t)g_srcidx[off + i] * STRIDE + lane];
            r = fmaxf(di * acc, 0.f);
        }
        if (lane < NPAIR) sy[local * 29 + lane] = r;
    }
    __syncthreads();

    // ---- gram partial ----
#pragma unroll
    for (int k = 0; k < 4; k++) {
        int e = tid + k * 256;
        if (e < 784) {
            int i = e / 28, j = e - i * 28;
            float a = 0.f;
#pragma unroll
            for (int nn = 0; nn < 32; nn++)
                a += sy[nn * 29 + i] * sy[nn * 29 + j];
            atomicAdd(&g_G[e], a);
        }
    }

    // ---- elect last block ----
    __threadfence();
    if (tid == 0) {
        int old = atomicAdd(&g_tick, 1);
        s_last = (old == gridDim.x - 1);
    }
    __syncthreads();
    if (!s_last) return;

    // ---- MLP (one block, coalesced W1 reads) ----
    for (int i = tid; i < 784; i += 256) sg[i] = __ldcg(&g_G[i]);
    __syncthreads();
    float wacc = 0.f;
#pragma unroll
    for (int o = 0; o < 16; o++) {
        int r = warp * 16 + o;
        const float* wr = W1 + (size_t)r * 784;
        float dot = 0.f;
        for (int m = lane; m < 784; m += 32) dot += wr[m] * sg[m];
#pragma unroll
        for (int off = 16; off; off >>= 1)
            dot += __shfl_xor_sync(~0u, dot, off);
        if (lane == 0) wacc += fmaxf(dot + b1[r], 0.f) * W2[r];
    }
    if (lane == 0) swacc[warp] = wacc;
    __syncthreads();
    if (tid == 0) {
        float z = b2[0];
#pragma unroll
        for (int w = 0; w < 8; w++) z += swacc[w];
        out[0] = 1.f / (1.f + expf(-z));
    }
}

extern "C" void kernel_launch(void* const* d_in, const int* in_sizes, int n_in,
                              void* d_out, int out_size) {
    const float* x  = (const float*)d_in[0];
    const int*   ei = (const int*)d_in[1];     // int32 (JAX x64 disabled)
    const float* qw = (const float*)d_in[2];
    const float* W1 = (const float*)d_in[3];
    const float* b1 = (const float*)d_in[4];
    const float* W2 = (const float*)d_in[5];
    const float* b2 = (const float*)d_in[6];
    int N = in_sizes[0] / NF;
    int E = in_sizes[1] / 2;
    int E4 = E >> 2;
    int ntiles = (N + TILE - 1) / TILE;

    k_setup     <<<(N + 255) / 256, 256>>>(qw, N);
    k_hist      <<<(E4 + 255) / 256, 256>>>(ei + E, E, N);
    k_scan      <<<ntiles, 1024>>>(N);
    k_feat      <<<(N + 31) / 32, 256>>>(x, N);
    k_fill      <<<(E4 + 255) / 256, 256>>>(ei, E, N);
    k_gathergram<<<(N + 31) / 32, 256>>>(N, W1, b1, W2, b2, (float*)d_out);
}

// round 9
// speedup vs baseline: 1.7540x; 1.1922x over previous
#include <cuda_runtime.h>
#include <cuda_fp16.h>
#include <math.h>

#define NQ 8
#define NF 256
#define NPAIR 28
#define STRIDE 32
#define MAXN 50176
#define MAXE 1600000
#define TILE 4096

// ---------------- static scratch ----------------
__device__ __half g_sfeat[MAXN * STRIDE]; // dinv-scaled features, fp16, 64B rows
__device__ int    g_cnt [MAXN];
__device__ int    g_off [MAXN];
__device__ int    g_cur [MAXN];
__device__ int    g_srcidx[MAXE];
__device__ float  g_dinv[MAXN];
__device__ float  g_coefs[NPAIR * 4];     // (B00, -B00, 2ReB01, pad)
__device__ float  g_G[784];
__device__ int    g_tick;

// ---------------- complex 2x2 helpers ----------------
__device__ __forceinline__ float2 cmul(float2 a, float2 b) {
    return make_float2(a.x * b.x - a.y * b.y, a.x * b.y + a.y * b.x);
}
__device__ __forceinline__ float2 cadd(float2 a, float2 b) {
    return make_float2(a.x + b.x, a.y + b.y);
}
__device__ __forceinline__ void mm2(const float2* A, const float2* B, float2* C) {
#pragma unroll
    for (int i = 0; i < 2; i++)
#pragma unroll
        for (int j = 0; j < 2; j++)
            C[i * 2 + j] = cadd(cmul(A[i * 2 + 0], B[0 * 2 + j]),
                                cmul(A[i * 2 + 1], B[1 * 2 + j]));
}

__device__ __forceinline__ float dot4(float4 a, float4 b) {
    return a.x * b.x + a.y * b.y + a.z * b.z + a.w * b.w;
}

// 'a' (first qubit) of pair f in combinations(range(8),2) order, as ALU chain
__device__ __forceinline__ int pair_a(int f) {
    return (f < 7) ? 0 : (f < 13) ? 1 : (f < 18) ? 2 : (f < 22) ? 3
         : (f < 25) ? 4 : (f < 27) ? 5 : 6;
}

// K1: coefficients + zero cnt/G/tick
__global__ void k_setup(const float* __restrict__ qw, int N) {
    int g = blockIdx.x * blockDim.x + threadIdx.x;
    if (g < N) g_cnt[g] = 0;
    if (g < 784) g_G[g] = 0.f;
    if (g == 800) g_tick = 0;
    if (g >= NPAIR) return;
    const float* p = qw + 6 * g;
    float2 M[4], T[4], R[4];
    float c, s;
    c = cosf(0.5f * p[0]); s = sinf(0.5f * p[0]);
    M[0] = make_float2(c, 0); M[1] = make_float2(0, -s);
    M[2] = make_float2(0, -s); M[3] = make_float2(c, 0);            // Rx(p0)
    c = cosf(0.5f * p[1]); s = sinf(0.5f * p[1]);
    R[0] = make_float2(c, 0); R[1] = make_float2(-s, 0);
    R[2] = make_float2(s, 0); R[3] = make_float2(c, 0);
    mm2(R, M, T);                                                   // Ry(p1)
    c = cosf(0.5f * p[2]); s = sinf(0.5f * p[2]);
    R[0] = make_float2(c, -s); R[1] = make_float2(0, 0);
    R[2] = make_float2(0, 0);  R[3] = make_float2(c, s);
    mm2(R, T, M);                                                   // Rz(p2)
    c = cosf(0.5f * p[3]); s = sinf(0.5f * p[3]);
    R[0] = make_float2(c, 0); R[1] = make_float2(0, -s);
    R[2] = make_float2(0, -s); R[3] = make_float2(c, 0);
    mm2(R, M, T);                                                   // Rx(p3)
    c = cosf(0.5f * p[4]); s = sinf(0.5f * p[4]);
    R[0] = make_float2(c, 0); R[1] = make_float2(-s, 0);
    R[2] = make_float2(s, 0); R[3] = make_float2(c, 0);
    mm2(R, T, M);                                                   // Ry(p4)
    c = cosf(0.5f * p[5]); s = sinf(0.5f * p[5]);
    R[0] = make_float2(c, -s); R[1] = make_float2(0, 0);
    R[2] = make_float2(0, 0);  R[3] = make_float2(c, s);
    mm2(R, M, T);                                                   // T = A
    float b00 = T[0].x * T[0].x + T[0].y * T[0].y
              - (T[2].x * T[2].x + T[2].y * T[2].y);
    float b01x2 = 2.f * (T[0].x * T[1].x + T[0].y * T[1].y
                       - T[2].x * T[3].x - T[2].y * T[3].y);
    g_coefs[g * 4 + 0] = b00;
    g_coefs[g * 4 + 1] = -b00;
    g_coefs[g * 4 + 2] = b01x2;
}

// K2: in-degree histogram, 8 edges/thread via 2x int4 (+ scalar tail)
__global__ void k_hist(const int* __restrict__ dst, int E, int N) {
    int t = blockIdx.x * blockDim.x + threadIdx.x;
    int E8 = E >> 3;
    if (t < E8) {
        int4 d0 = ((const int4*)dst)[2 * t];
        int4 d1 = ((const int4*)dst)[2 * t + 1];
        if ((unsigned)d0.x < (unsigned)N) atomicAdd(&g_cnt[d0.x], 1);
        if ((unsigned)d0.y < (unsigned)N) atomicAdd(&g_cnt[d0.y], 1);
        if ((unsigned)d0.z < (unsigned)N) atomicAdd(&g_cnt[d0.z], 1);
        if ((unsigned)d0.w < (unsigned)N) atomicAdd(&g_cnt[d0.w], 1);
        if ((unsigned)d1.x < (unsigned)N) atomicAdd(&g_cnt[d1.x], 1);
        if ((unsigned)d1.y < (unsigned)N) atomicAdd(&g_cnt[d1.y], 1);
        if ((unsigned)d1.z < (unsigned)N) atomicAdd(&g_cnt[d1.z], 1);
        if ((unsigned)d1.w < (unsigned)N) atomicAdd(&g_cnt[d1.w], 1);
    }
    if (t == 0)
        for (int e = E8 * 8; e < E; e++) {
            int d = dst[e];
            if ((unsigned)d < (unsigned)N) atomicAdd(&g_cnt[d], 1);
        }
}

// K3: fused scan. Each block sums its prefix tiles, then scans its own tile.
__global__ void k_scan(int N) {
    __shared__ int sred[32];
    __shared__ int swsum[32];
    __shared__ int swpre[32];
    __shared__ int s_prefix;
    int b = blockIdx.x, t = threadIdx.x;
    int lane = t & 31, warp = t >> 5;
    int ps = 0;
    for (int i = t; i < b * TILE; i += 1024) ps += g_cnt[i];
#pragma unroll
    for (int off = 16; off; off >>= 1) ps += __shfl_xor_sync(~0u, ps, off);
    if (lane == 0) sred[warp] = ps;
    __syncthreads();
    if (warp == 0) {
        int v = sred[lane];
#pragma unroll
        for (int off = 16; off; off >>= 1) v += __shfl_xor_sync(~0u, v, off);
        if (lane == 0) s_prefix = v;
    }
    int base = b * TILE + t * 4;
    int v[4], pre[4];
    int run = 0;
#pragma unroll
    for (int k = 0; k < 4; k++) {
        int i = base + k;
        v[k] = (i < N) ? g_cnt[i] : 0;
        pre[k] = run;
        run += v[k];
    }
    int incl = run;
#pragma unroll
    for (int off = 1; off < 32; off <<= 1) {
        int u = __shfl_up_sync(~0u, incl, off);
        if (lane >= off) incl += u;
    }
    if (lane == 31) swsum[warp] = incl;
    int texcl = incl - run;
    __syncthreads();
    if (warp == 0) {
        int w = swsum[lane];
        int wi = w;
#pragma unroll
        for (int off = 1; off < 32; off <<= 1) {
            int u = __shfl_up_sync(~0u, wi, off);
            if (lane >= off) wi += u;
        }
        swpre[lane] = wi - w;
    }
    __syncthreads();
    int tilebase = s_prefix + swpre[warp] + texcl;
#pragma unroll
    for (int k = 0; k < 4; k++) {
        int i = base + k;
        if (i < N) {
            int excl = tilebase + pre[k];
            g_off[i] = excl;
            g_cur[i] = excl;
            g_dinv[i] = rsqrtf((float)(v[k] + 1));
        }
    }
}

// feat body: 4 nodes/warp, 8 lanes/node, 32 values/lane in registers.
__device__ __forceinline__ void feat_body(const float* __restrict__ x, int N,
                                          int blk) {
    __shared__ float4 smw[8][256];
    int lane = threadIdx.x & 31;
    int warp = threadIdx.x >> 5;
    int g    = lane & 7;
    int sub  = lane >> 3;
    int node = blk * 32 + warp * 4 + sub;
    int nclamp = node < N ? node : N - 1;

    const float4* xr = (const float4*)(x + (size_t)nclamp * NF);
    float4 v[8];
#pragma unroll
    for (int sg = 0; sg < 8; sg++) v[sg] = xr[sg * 8 + g];

    float4* sw = &smw[warp][sub * 64];
#pragma unroll
    for (int sg = 0; sg < 8; sg++) sw[sg * 8 + g] = v[sg];
    __syncwarp();

    float s2 = 0.f, p0 = 0.f, p1 = 0.f, p2 = 0.f, p6 = 0.f, t6 = 0.f;
#pragma unroll
    for (int sg = 0; sg < 8; sg++) {
        float4 a = v[sg];
        float nn = dot4(a, a);
        s2 += nn;
        p0 += (sg & 4) ? -nn : nn;
        p1 += (sg & 2) ? -nn : nn;
        p2 += (sg & 1) ? -nn : nn;
        p6 += a.x * a.x + a.y * a.y - a.z * a.z - a.w * a.w;
        t6 += a.x * a.z + a.y * a.w;
    }
    float t0 = dot4(v[0], v[4]) + dot4(v[1], v[5])
             + dot4(v[2], v[6]) + dot4(v[3], v[7]);
    float t1 = dot4(v[0], v[2]) + dot4(v[1], v[3])
             + dot4(v[4], v[6]) + dot4(v[5], v[7]);
    float t2 = dot4(v[0], v[1]) + dot4(v[2], v[3])
             + dot4(v[4], v[5]) + dot4(v[6], v[7]);

    float t3 = 0.f, t4 = 0.f, t5 = 0.f;
#pragma unroll
    for (int sg = 0; sg < 8; sg++) t3 += dot4(v[sg], sw[sg * 8 + (g ^ 4)]);
#pragma unroll
    for (int sg = 0; sg < 8; sg++) t4 += dot4(v[sg], sw[sg * 8 + (g ^ 2)]);
#pragma unroll
    for (int sg = 0; sg < 8; sg++) t5 += dot4(v[sg], sw[sg * 8 + (g ^ 1)]);

#define RED8(a) { a += __shfl_xor_sync(~0u, a, 1); \
                  a += __shfl_xor_sync(~0u, a, 2); \
                  a += __shfl_xor_sync(~0u, a, 4); }
    RED8(p0) RED8(p1) RED8(p2) RED8(p6)
    RED8(t0) RED8(t1) RED8(t2) RED8(t6)
    RED8(t3) RED8(t4) RED8(t5)
    t3 *= 0.5f; t4 *= 0.5f; t5 *= 0.5f;

    float r0  = s2 + __shfl_xor_sync(~0u, s2, 1);
    float r1  = s2 + __shfl_xor_sync(~0u, s2, 2);
    float r01 = r0 + __shfl_xor_sync(~0u, r0, 2);
    float r02 = r0 + __shfl_xor_sync(~0u, r0, 4);
    float r12 = r1 + __shfl_xor_sync(~0u, r1, 4);
    float ssr = r01 + __shfl_xor_sync(~0u, r01, 4);
    float u3  = r01 - __shfl_xor_sync(~0u, r01, 4);
    float u4  = r02 - __shfl_xor_sync(~0u, r02, 2);
    float u5  = r12 - __shfl_xor_sync(~0u, r12, 1);
    float q3v = ((g >> 2) & 1) ? -u3 : u3;
    float q4v = ((g >> 1) & 1) ? -u4 : u4;
    float q5v = (g & 1) ? -u5 : u5;

    float smv[7] = {p0, p1, p2, q3v, q4v, q5v, p6};
    float tqv[7] = {t0, t1, t2, t3, t4, t5, t6};

    float di = g_dinv[nclamp];
    float inv_ss = 1.f / ssr;
#pragma unroll
    for (int k = 0; k < 4; k++) {
        int f = g + 8 * k;
        float outv = 0.f;
        if (f < NPAIR) {
            int a = pair_a(f);
            float S = 0.f, Tv = 0.f;
#pragma unroll
            for (int q = 0; q < 7; q++)
                if (a == q) { S = smv[q]; Tv = tqv[q]; }
            float S0 = 0.5f * (ssr + S);
            float S1 = ssr - S0;
            float4 co = *(const float4*)&g_coefs[f * 4];
            float e = (co.x * S0 + co.y * S1 + co.z * Tv) * inv_ss;
            outv = (0.5f + 0.5f * e) * di;
        }
        if (node < N) g_sfeat[(size_t)node * STRIDE + f] = __float2half(outv);
    }
#undef RED8
}

// fill body: CSR fill, 4 edges/thread (+ scalar tail)
__device__ __forceinline__ void fill_body(const int* __restrict__ ei, int E,
                                          int N, int blk) {
    int t = blk * 256 + threadIdx.x;
    int E4 = E >> 2;
    if (t < E4) {
        int4 s = ((const int4*)ei)[t];
        int4 d = ((const int4*)(ei + E))[t];
        if ((unsigned)d.x < (unsigned)N) g_srcidx[atomicAdd(&g_cur[d.x], 1)] = s.x;
        if ((unsigned)d.y < (unsigned)N) g_srcidx[atomicAdd(&g_cur[d.y], 1)] = s.y;
        if ((unsigned)d.z < (unsigned)N) g_srcidx[atomicAdd(&g_cur[d.z], 1)] = s.z;
        if ((unsigned)d.w < (unsigned)N) g_srcidx[atomicAdd(&g_cur[d.w], 1)] = s.w;
    }
    if (t == 0)
        for (int e = E4 * 4; e < E; e++) {
            int s = ei[e], d = ei[E + e];
            if ((unsigned)d < (unsigned)N) g_srcidx[atomicAdd(&g_cur[d], 1)] = s;
        }
}

// K4: block-specialized feat || fill (both depend only on k_scan)
__global__ void k_featfill(const float* __restrict__ x,
                           const int* __restrict__ ei, int E, int N,
                           int nFeatBlk) {
    if ((int)blockIdx.x < nFeatBlk) feat_body(x, N, blockIdx.x);
    else                            fill_body(ei, E, N, blockIdx.x - nFeatBlk);
}

// K5: fused gather + gram + (last block) MLP.
__global__ void k_gathergram(int N,
                             const float* __restrict__ W1,
                             const float* __restrict__ b1,
                             const float* __restrict__ W2,
                             const float* __restrict__ b2,
                             float* __restrict__ out) {
    __shared__ float sy[32 * 29];
    __shared__ float sg[784];
    __shared__ float swacc[8];
    __shared__ int   s_last;
    int tid = threadIdx.x;
    int warp = tid >> 5, lane = tid & 31;
    int base = blockIdx.x * 32;

    // ---- gather: each warp handles 4 nodes ----
#pragma unroll
    for (int k = 0; k < 4; k++) {
        int local = warp * 4 + k;
        int node = base + local;
        float r = 0.f;
        if (node < N) {
            int off = g_off[node];
            int cnt = g_cnt[node];
            float di = g_dinv[node];
            float acc = __half2float(g_sfeat[(size_t)node * STRIDE + lane]);
            int i = 0;
            for (; i + 4 <= cnt; i += 4) {
                int s0 = g_srcidx[off + i];
                int s1 = g_srcidx[off + i + 1];
                int s2 = g_srcidx[off + i + 2];
                int s3 = g_srcidx[off + i + 3];
                float f0 = __half2float(g_sfeat[(size_t)s0 * STRIDE + lane]);
                float f1 = __half2float(g_sfeat[(size_t)s1 * STRIDE + lane]);
                float f2 = __half2float(g_sfeat[(size_t)s2 * STRIDE + lane]);
                float f3 = __half2float(g_sfeat[(size_t)s3 * STRIDE + lane]);
                acc += (f0 + f1) + (f2 + f3);
            }
            for (; i < cnt; i++)
                acc += __half2float(g_sfeat[(size_t)g_srcidx[off + i] * STRIDE + lane]);
            r = fmaxf(di * acc, 0.f);
        }
        if (lane < NPAIR) sy[local * 29 + lane] = r;
    }
    __syncthreads();

    // ---- gram partial ----
#pragma unroll
    for (int k = 0; k < 4; k++) {
        int e = tid + k * 256;
        if (e < 784) {
            int i = e / 28, j = e - i * 28;
            float a = 0.f;
#pragma unroll
            for (int nn = 0; nn < 32; nn++)
                a += sy[nn * 29 + i] * sy[nn * 29 + j];
            atomicAdd(&g_G[e], a);
        }
    }

    // ---- elect last block ----
    __threadfence();
    if (tid == 0) {
        int old = atomicAdd(&g_tick, 1);
        s_last = (old == gridDim.x - 1);
    }
    __syncthreads();
    if (!s_last) return;

    // ---- MLP (one block, coalesced W1 reads) ----
    for (int i = tid; i < 784; i += 256) sg[i] = __ldcg(&g_G[i]);
    __syncthreads();
    float wacc = 0.f;
#pragma unroll
    for (int o = 0; o < 16; o++) {
        int r = warp * 16 + o;
        const float* wr = W1 + (size_t)r * 784;
        float dot = 0.f;
        for (int m = lane; m < 784; m += 32) dot += wr[m] * sg[m];
#pragma unroll
        for (int off = 16; off; off >>= 1)
            dot += __shfl_xor_sync(~0u, dot, off);
        if (lane == 0) wacc += fmaxf(dot + b1[r], 0.f) * W2[r];
    }
    if (lane == 0) swacc[warp] = wacc;
    __syncthreads();
    if (tid == 0) {
        float z = b2[0];
#pragma unroll
        for (int w = 0; w < 8; w++) z += swacc[w];
        out[0] = 1.f / (1.f + expf(-z));
    }
}

extern "C" void kernel_launch(void* const* d_in, const int* in_sizes, int n_in,
                              void* d_out, int out_size) {
    const float* x  = (const float*)d_in[0];
    const int*   ei = (const int*)d_in[1];     // int32 (JAX x64 disabled)
    const float* qw = (const float*)d_in[2];
    const float* W1 = (const float*)d_in[3];
    const float* b1 = (const float*)d_in[4];
    const float* W2 = (const float*)d_in[5];
    const float* b2 = (const float*)d_in[6];
    int N = in_sizes[0] / NF;
    int E = in_sizes[1] / 2;
    int E4 = E >> 2;
    int E8 = E >> 3;
    int ntiles = (N + TILE - 1) / TILE;
    int nFeatBlk = (N + 31) / 32;
    int nFillBlk = (E4 + 255) / 256;

    k_setup     <<<(N + 255) / 256, 256>>>(qw, N);
    k_hist      <<<(E8 + 255) / 256, 256>>>(ei + E, E, N);
    k_scan      <<<ntiles, 1024>>>(N);
    k_featfill  <<<nFeatBlk + nFillBlk, 256>>>(x, ei, E, N, nFeatBlk);
    k_gathergram<<<(N + 31) / 32, 256>>>(N, W1, b1, W2, b2, (float*)d_out);
}